// round 12
// baseline (speedup 1.0000x reference)
#include <cuda_runtime.h>
#include <cuda_bf16.h>
#include <math.h>

// ---------------- problem constants ----------------
#define S_LEN   2048
#define D_DIM   2048
#define KV_DIM  256
#define DFF_DIM 5632
#define BSL     4096          // B * S
#define EPSV    1e-6f

typedef __nv_bfloat16 bf16;

// ---------------- scratch (device globals; no allocation allowed) ----------
__device__ float g_PM [(size_t)S_LEN * D_DIM ];     // pm0 + pm1
// split (hi/lo) bf16 weights, rope folded into WQ/WK
__device__ bf16 g_WQh[(size_t)D_DIM  * D_DIM ], g_WQl[(size_t)D_DIM  * D_DIM ];
__device__ bf16 g_WKh[(size_t)KV_DIM * D_DIM ], g_WKl[(size_t)KV_DIM * D_DIM ];
__device__ bf16 g_WVh[(size_t)KV_DIM * D_DIM ], g_WVl[(size_t)KV_DIM * D_DIM ];
__device__ bf16 g_WOh[(size_t)D_DIM  * D_DIM ], g_WOl[(size_t)D_DIM  * D_DIM ];
__device__ bf16 g_GWh[(size_t)DFF_DIM* D_DIM ], g_GWl[(size_t)DFF_DIM* D_DIM ];
__device__ bf16 g_UWh[(size_t)DFF_DIM* D_DIM ], g_UWl[(size_t)DFF_DIM* D_DIM ];
__device__ bf16 g_DWh[(size_t)D_DIM  *DFF_DIM], g_DWl[(size_t)D_DIM  *DFF_DIM];
// split activations
__device__ bf16 g_Hh [(size_t)BSL * D_DIM ], g_Hl [(size_t)BSL * D_DIM ];
__device__ bf16 g_ATh[(size_t)BSL * D_DIM ], g_ATl[(size_t)BSL * D_DIM ];
__device__ bf16 g_Gh [(size_t)BSL * DFF_DIM], g_Gl[(size_t)BSL * DFF_DIM];
// fp32 intermediates
__device__ float g_Q  [(size_t)BSL * D_DIM ];
__device__ float g_K  [(size_t)BSL * KV_DIM];
__device__ float g_V  [(size_t)BSL * KV_DIM];
__device__ float g_X2 [(size_t)BSL * D_DIM ];
__device__ float g_Gs [(size_t)BSL * DFF_DIM];

// ---------------- helpers ----------------
__device__ __forceinline__ void split_f(float a, bf16 &h, bf16 &l) {
    h = __float2bfloat16(a);
    l = __float2bfloat16(a - __bfloat162float(h));
}

__device__ __forceinline__ void ldsm4(unsigned &r0, unsigned &r1,
                                      unsigned &r2, unsigned &r3, unsigned addr) {
    asm volatile("ldmatrix.sync.aligned.m8n8.x4.shared.b16 {%0,%1,%2,%3}, [%4];"
                 : "=r"(r0), "=r"(r1), "=r"(r2), "=r"(r3) : "r"(addr));
}
__device__ __forceinline__ void ldsm2(unsigned &r0, unsigned &r1, unsigned addr) {
    asm volatile("ldmatrix.sync.aligned.m8n8.x2.shared.b16 {%0,%1}, [%2];"
                 : "=r"(r0), "=r"(r1) : "r"(addr));
}
__device__ __forceinline__ void mma_bf16(float* c, const unsigned* a, const unsigned* b) {
    asm volatile("mma.sync.aligned.m16n8k16.row.col.f32.bf16.bf16.f32 "
                 "{%0,%1,%2,%3}, {%4,%5,%6,%7}, {%8,%9}, {%0,%1,%2,%3};"
                 : "+f"(c[0]), "+f"(c[1]), "+f"(c[2]), "+f"(c[3])
                 : "r"(a[0]), "r"(a[1]), "r"(a[2]), "r"(a[3]),
                   "r"(b[0]), "r"(b[1]));
}

// ---------------- prep kernels ----------------
__global__ void pmsum_k(const float* __restrict__ pm, float* __restrict__ out) {
    size_t i = ((size_t)blockIdx.x * 256 + threadIdx.x) * 4;
    float4 a = *(const float4*)&pm[i];
    float4 b = *(const float4*)&pm[(size_t)S_LEN * D_DIM + i];
    *(float4*)&out[i] = make_float4(a.x + b.x, a.y + b.y, a.z + b.z, a.w + b.w);
}

__device__ __forceinline__ void store_split4(bf16* oh, bf16* ol, size_t i, float4 v) {
    bf16 h0, l0, h1, l1, h2, l2, h3, l3;
    split_f(v.x, h0, l0); split_f(v.y, h1, l1);
    split_f(v.z, h2, l2); split_f(v.w, h3, l3);
    *(__nv_bfloat162*)&oh[i]     = __halves2bfloat162(h0, h1);
    *(__nv_bfloat162*)&oh[i + 2] = __halves2bfloat162(h2, h3);
    *(__nv_bfloat162*)&ol[i]     = __halves2bfloat162(l0, l1);
    *(__nv_bfloat162*)&ol[i + 2] = __halves2bfloat162(l2, l3);
}

__global__ void split_k(const float* __restrict__ w, bf16* __restrict__ oh,
                        bf16* __restrict__ ol) {
    size_t i = ((size_t)blockIdx.x * 256 + threadIdx.x) * 4;
    store_split4(oh, ol, i, *(const float4*)&w[i]);
}

// rope-rotate rows then split: out[c][k] = sgn * w[src][k]   (K dim = 2048)
__global__ void rotate_split_k(const float* __restrict__ w, bf16* __restrict__ oh,
                               bf16* __restrict__ ol, int half) {
    size_t i = ((size_t)blockIdx.x * 256 + threadIdx.x) * 4;
    int c = (int)(i >> 11);
    int k = (int)(i & 2047);
    int src = (c < half) ? (c + half) : (c - half);
    float sgn = (c < half) ? -1.f : 1.f;
    float4 v = *(const float4*)&w[(size_t)src * D_DIM + k];
    store_split4(oh, ol, i, make_float4(sgn*v.x, sgn*v.y, sgn*v.z, sgn*v.w));
}

// ---------------- rmsnorm -> split bf16 ----------------
__global__ __launch_bounds__(256) void rmsnorm_bf_k(const float* __restrict__ x,
                                                    const float* __restrict__ w,
                                                    bf16* __restrict__ oh,
                                                    bf16* __restrict__ ol) {
    int row = blockIdx.x;
    const float* xr = x + (size_t)row * D_DIM;
    size_t obase = (size_t)row * D_DIM;
    int t = threadIdx.x;
    float4 v0 = *(const float4*)&xr[t * 4];
    float4 v1 = *(const float4*)&xr[1024 + t * 4];
    float ss = v0.x*v0.x + v0.y*v0.y + v0.z*v0.z + v0.w*v0.w
             + v1.x*v1.x + v1.y*v1.y + v1.z*v1.z + v1.w*v1.w;
    #pragma unroll
    for (int off = 16; off; off >>= 1) ss += __shfl_xor_sync(0xffffffffu, ss, off);
    __shared__ float red[8];
    if ((t & 31) == 0) red[t >> 5] = ss;
    __syncthreads();
    float tot = red[0]+red[1]+red[2]+red[3]+red[4]+red[5]+red[6]+red[7];
    float sc = 1.f / (sqrtf(tot * (1.f / 2048.f) + EPSV) + EPSV);
    float4 w0 = *(const float4*)&w[t * 4];
    float4 w1 = *(const float4*)&w[1024 + t * 4];
    store_split4(oh, ol, obase + t * 4,
                 make_float4(v0.x*sc*w0.x, v0.y*sc*w0.y, v0.z*sc*w0.z, v0.w*sc*w0.w));
    store_split4(oh, ol, obase + 1024 + t * 4,
                 make_float4(v1.x*sc*w1.x, v1.y*sc*w1.y, v1.z*sc*w1.z, v1.w*sc*w1.w));
}

// ---------------- tensor-core GEMM (3xbf16 split, fp32 accuracy) ------------
//   C[M,N] = (Ah+Al)[M,K] @ (Bh+Bl)[N,K]^T   (Al*Bl term dropped)
// EPI: 0 plain | 1 *PM[(r&2047)*D+c] | 2 +aux[r*N+c] | 3 silu | 4 *aux[r*N+c]
// OUT: 0 fp32 C | 1 split bf16 (Ch, Cl)
#define TBM 128
#define TBN 128
#define TBK 32
#define SROW 40      // 32 + 8 pad -> 80B stride, conflict-free ldmatrix

template<int EPI>
__device__ __forceinline__ float epi_apply(float x, const float* __restrict__ aux,
                                           int r, int c, int N) {
    if (EPI == 1)      x *= aux[(size_t)(r & (S_LEN - 1)) * D_DIM + c];
    else if (EPI == 2) x += aux[(size_t)r * N + c];
    else if (EPI == 3) x  = x / (1.f + __expf(-x));
    else if (EPI == 4) x *= aux[(size_t)r * N + c];
    return x;
}

template<int EPI, int OUT>
__global__ __launch_bounds__(256) void mma_gemm(const bf16* __restrict__ Ah,
                                                const bf16* __restrict__ Al,
                                                const bf16* __restrict__ Bh,
                                                const bf16* __restrict__ Bl,
                                                float* __restrict__ C,
                                                bf16* __restrict__ Ch,
                                                bf16* __restrict__ Cl,
                                                int M, int N, int K,
                                                const float* __restrict__ aux) {
    __shared__ __align__(16) bf16 sAh[TBM * SROW];
    __shared__ __align__(16) bf16 sAl[TBM * SROW];
    __shared__ __align__(16) bf16 sBh[TBN * SROW];
    __shared__ __align__(16) bf16 sBl[TBN * SROW];

    int t = threadIdx.x;
    int lane = t & 31, wid = t >> 5;
    int wm = wid & 1, wn = wid >> 1;       // 2 x 4 warp grid, warp tile 64x32
    int m0 = blockIdx.y * TBM, n0 = blockIdx.x * TBN;

    // global loads: each thread loads a 16-elem row segment of each tile
    int lr = t >> 1;                // 0..127
    int lcb = (t & 1) * 16;         // 0 / 16
    const bf16* pAh = Ah + (size_t)(m0 + lr) * K + lcb;
    const bf16* pAl = Al + (size_t)(m0 + lr) * K + lcb;
    const bf16* pBh = Bh + (size_t)(n0 + lr) * K + lcb;
    const bf16* pBl = Bl + (size_t)(n0 + lr) * K + lcb;

    uint4 rah0 = *(const uint4*)(pAh),     rah1 = *(const uint4*)(pAh + 8);
    uint4 ral0 = *(const uint4*)(pAl),     ral1 = *(const uint4*)(pAl + 8);
    uint4 rbh0 = *(const uint4*)(pBh),     rbh1 = *(const uint4*)(pBh + 8);
    uint4 rbl0 = *(const uint4*)(pBl),     rbl1 = *(const uint4*)(pBl + 8);

    float acc[4][4][4];
    #pragma unroll
    for (int i = 0; i < 4; i++)
        #pragma unroll
        for (int j = 0; j < 4; j++)
            #pragma unroll
            for (int k = 0; k < 4; k++) acc[i][j][k] = 0.f;

    unsigned bAh = (unsigned)__cvta_generic_to_shared(sAh);
    unsigned bAl = (unsigned)__cvta_generic_to_shared(sAl);
    unsigned bBh = (unsigned)__cvta_generic_to_shared(sBh);
    unsigned bBl = (unsigned)__cvta_generic_to_shared(sBl);

    // ldmatrix lane offsets (bytes)
    unsigned aoff = ((unsigned)((wm * 64 + (lane & 15)) * SROW + ((lane & 16) >> 1))) * 2;
    unsigned boff = ((unsigned)((wn * 32 + (lane & 7)) * SROW + (lane & 8))) * 2;
    unsigned soff = (unsigned)(lr * SROW + lcb);   // element offset for stores

    for (int k0 = 0; k0 < K; k0 += TBK) {
        __syncthreads();
        *(uint4*)&sAh[soff] = rah0;  *(uint4*)&sAh[soff + 8] = rah1;
        *(uint4*)&sAl[soff] = ral0;  *(uint4*)&sAl[soff + 8] = ral1;
        *(uint4*)&sBh[soff] = rbh0;  *(uint4*)&sBh[soff + 8] = rbh1;
        *(uint4*)&sBl[soff] = rbl0;  *(uint4*)&sBl[soff + 8] = rbl1;
        __syncthreads();

        if (k0 + TBK < K) {
            int kn = k0 + TBK;
            rah0 = *(const uint4*)(pAh + kn);  rah1 = *(const uint4*)(pAh + kn + 8);
            ral0 = *(const uint4*)(pAl + kn);  ral1 = *(const uint4*)(pAl + kn + 8);
            rbh0 = *(const uint4*)(pBh + kn);  rbh1 = *(const uint4*)(pBh + kn + 8);
            rbl0 = *(const uint4*)(pBl + kn);  rbl1 = *(const uint4*)(pBl + kn + 8);
        }

        #pragma unroll
        for (int ks = 0; ks < 2; ks++) {
            unsigned fah[4][4], fal[4][4], fbh[4][2], fbl[4][2];
            #pragma unroll
            for (int mi = 0; mi < 4; mi++) {
                unsigned od = aoff + (unsigned)(mi * 16 * SROW * 2) + (unsigned)(ks * 32);
                ldsm4(fah[mi][0], fah[mi][1], fah[mi][2], fah[mi][3], bAh + od);
                ldsm4(fal[mi][0], fal[mi][1], fal[mi][2], fal[mi][3], bAl + od);
            }
            #pragma unroll
            for (int ni = 0; ni < 4; ni++) {
                unsigned od = boff + (unsigned)(ni * 8 * SROW * 2) + (unsigned)(ks * 32);
                ldsm2(fbh[ni][0], fbh[ni][1], bBh + od);
                ldsm2(fbl[ni][0], fbl[ni][1], bBl + od);
            }
            #pragma unroll
            for (int mi = 0; mi < 4; mi++)
                #pragma unroll
                for (int ni = 0; ni < 4; ni++) {
                    mma_bf16(acc[mi][ni], fah[mi], fbh[ni]);
                    mma_bf16(acc[mi][ni], fah[mi], fbl[ni]);
                    mma_bf16(acc[mi][ni], fal[mi], fbh[ni]);
                }
        }
    }

    // ------------- epilogue -------------
    int gid = lane >> 2;
    int c2  = (lane & 3) * 2;
    #pragma unroll
    for (int mi = 0; mi < 4; mi++) {
        #pragma unroll
        for (int ni = 0; ni < 4; ni++) {
            int r = m0 + wm * 64 + mi * 16 + gid;
            int c = n0 + wn * 32 + ni * 8 + c2;
            #pragma unroll
            for (int half = 0; half < 2; half++) {
                int rr = r + half * 8;
                float v0 = epi_apply<EPI>(acc[mi][ni][half*2 + 0], aux, rr, c,   N);
                float v1 = epi_apply<EPI>(acc[mi][ni][half*2 + 1], aux, rr, c+1, N);
                if (OUT == 0) {
                    *(float2*)&C[(size_t)rr * N + c] = make_float2(v0, v1);
                } else {
                    bf16 h0, l0, h1, l1;
                    split_f(v0, h0, l0);  split_f(v1, h1, l1);
                    *(__nv_bfloat162*)&Ch[(size_t)rr * N + c] = __halves2bfloat162(h0, h1);
                    *(__nv_bfloat162*)&Cl[(size_t)rr * N + c] = __halves2bfloat162(l0, l1);
                }
            }
        }
    }
}

// ---------------- attention: flash-style 64x64 streaming tile ----------------
// attn = exp(Q K^T * scale) ; out = (attn @ V) / (rowsum + 1)  -> split bf16
#define ATT_SMEM_BYTES ((4096 + 4160 + 4096) * 4)   // Qs[64*64] KP[64*65] Vs[64*64]

__global__ __launch_bounds__(256) void attn_k(const float* __restrict__ Qg,
                                              const float* __restrict__ Kg,
                                              const float* __restrict__ Vg,
                                              bf16* __restrict__ Oh,
                                              bf16* __restrict__ Ol) {
    extern __shared__ __align__(16) float sm[];
    float* Qs = sm;
    float* KP = sm + 4096;        // K tile, then reused for P = exp(scores)
    float* Vs = sm + 4096 + 4160;
    const float scale = 1.0f / (16.0f + 1e-6f);   // 1/(sqrt(256)+eps)

    int t  = threadIdx.x;
    int tx = t & 15, ty = t >> 4;
    int q0 = blockIdx.x << 6;
    int bh = blockIdx.y;
    int b = bh >> 5, hd = bh & 31;
    const float* Qb = Qg + ((size_t)(b * S_LEN + q0)) * D_DIM + hd * 64;
    const float* Kb = Kg + (size_t)b * S_LEN * KV_DIM + (hd & 3) * 64;
    const float* Vb = Vg + (size_t)b * S_LEN * KV_DIM + (hd & 3) * 64;

    int lr = t >> 2;
    int lc = (t & 3) << 4;
    {   // load + pre-scale Q tile
        const float* src = Qb + (size_t)lr * D_DIM + lc;
        float* dst = Qs + lr * 64 + lc;
        #pragma unroll
        for (int i = 0; i < 16; i += 4) {
            float4 v = *(const float4*)(src + i);
            *(float4*)(dst + i) = make_float4(v.x*scale, v.y*scale, v.z*scale, v.w*scale);
        }
    }

    float accO[4][4];
    float den[4];
    #pragma unroll
    for (int i = 0; i < 4; i++) {
        den[i] = 0.f;
        #pragma unroll
        for (int j = 0; j < 4; j++) accO[i][j] = 0.f;
    }

    for (int kt = 0; kt < 32; kt++) {
        __syncthreads();
        {   // load K (stride-65 rows) and V tiles
            const float* ks = Kb + (size_t)(kt * 64 + lr) * KV_DIM + lc;
            const float* vs = Vb + (size_t)(kt * 64 + lr) * KV_DIM + lc;
            #pragma unroll
            for (int i = 0; i < 16; i += 4) {
                float4 kv = *(const float4*)(ks + i);
                KP[lr*65 + lc + i + 0] = kv.x;
                KP[lr*65 + lc + i + 1] = kv.y;
                KP[lr*65 + lc + i + 2] = kv.z;
                KP[lr*65 + lc + i + 3] = kv.w;
                *(float4*)(Vs + lr*64 + lc + i) = *(const float4*)(vs + i);
            }
        }
        __syncthreads();
        float sc[4][4] = {};
        #pragma unroll 8
        for (int k = 0; k < 64; k++) {
            float q[4], kk[4];
            #pragma unroll
            for (int i = 0; i < 4; i++) q[i]  = Qs[(4*ty + i) * 64 + k];
            #pragma unroll
            for (int j = 0; j < 4; j++) kk[j] = KP[(4*tx + j) * 65 + k];
            #pragma unroll
            for (int i = 0; i < 4; i++)
                #pragma unroll
                for (int j = 0; j < 4; j++) sc[i][j] += q[i] * kk[j];
        }
        __syncthreads();
        #pragma unroll
        for (int i = 0; i < 4; i++)
            #pragma unroll
            for (int j = 0; j < 4; j++)
                KP[(4*ty + i) * 65 + 4*tx + j] = __expf(sc[i][j]);
        __syncthreads();
        #pragma unroll 8
        for (int k = 0; k < 64; k++) {
            float p[4];
            #pragma unroll
            for (int i = 0; i < 4; i++) p[i] = KP[(4*ty + i) * 65 + k];
            float4 vv = *(const float4*)&Vs[k * 64 + 4*tx];
            #pragma unroll
            for (int i = 0; i < 4; i++) {
                accO[i][0] += p[i] * vv.x;
                accO[i][1] += p[i] * vv.y;
                accO[i][2] += p[i] * vv.z;
                accO[i][3] += p[i] * vv.w;
                den[i]     += p[i];
            }
        }
    }

    size_t obase = ((size_t)(b * S_LEN + q0)) * D_DIM + hd * 64;
    #pragma unroll
    for (int i = 0; i < 4; i++) {
        float inv = 1.f / (den[i] + 1.f);
        float v0 = accO[i][0]*inv, v1 = accO[i][1]*inv;
        float v2 = accO[i][2]*inv, v3 = accO[i][3]*inv;
        bf16 h0,l0,h1,l1,h2,l2,h3,l3;
        split_f(v0,h0,l0); split_f(v1,h1,l1); split_f(v2,h2,l2); split_f(v3,h3,l3);
        size_t off = obase + (size_t)(4*ty + i) * D_DIM + 4*tx;
        *(__nv_bfloat162*)&Oh[off]     = __halves2bfloat162(h0, h1);
        *(__nv_bfloat162*)&Oh[off + 2] = __halves2bfloat162(h2, h3);
        *(__nv_bfloat162*)&Ol[off]     = __halves2bfloat162(l0, l1);
        *(__nv_bfloat162*)&Ol[off + 2] = __halves2bfloat162(l2, l3);
    }
}

// ---------------- launcher ----------------
extern "C" void kernel_launch(void* const* d_in, const int* in_sizes, int n_in,
                              void* d_out, int out_size) {
    (void)in_sizes; (void)n_in; (void)out_size;
    const float* x   = (const float*)d_in[0];
    const float* pm  = (const float*)d_in[1];
    const float* wna = (const float*)d_in[2];
    const float* wnf = (const float*)d_in[3];
    const float* wq  = (const float*)d_in[4];
    const float* wk  = (const float*)d_in[5];
    const float* wv  = (const float*)d_in[6];
    const float* wo  = (const float*)d_in[7];
    const float* gw  = (const float*)d_in[8];
    const float* uw  = (const float*)d_in[9];
    const float* dw  = (const float*)d_in[10];
    float* out = (float*)d_out;

    float *PM, *Qp, *Kp, *Vp, *X2, *Gs;
    bf16 *WQh,*WQl,*WKh,*WKl,*WVh,*WVl,*WOh,*WOl,*GWh,*GWl,*UWh,*UWl,*DWh,*DWl;
    bf16 *Hh,*Hl,*ATh,*ATl,*Gh,*Gl;
    cudaGetSymbolAddress((void**)&PM,  g_PM);
    cudaGetSymbolAddress((void**)&Qp,  g_Q);
    cudaGetSymbolAddress((void**)&Kp,  g_K);
    cudaGetSymbolAddress((void**)&Vp,  g_V);
    cudaGetSymbolAddress((void**)&X2,  g_X2);
    cudaGetSymbolAddress((void**)&Gs,  g_Gs);
    cudaGetSymbolAddress((void**)&WQh, g_WQh); cudaGetSymbolAddress((void**)&WQl, g_WQl);
    cudaGetSymbolAddress((void**)&WKh, g_WKh); cudaGetSymbolAddress((void**)&WKl, g_WKl);
    cudaGetSymbolAddress((void**)&WVh, g_WVh); cudaGetSymbolAddress((void**)&WVl, g_WVl);
    cudaGetSymbolAddress((void**)&WOh, g_WOh); cudaGetSymbolAddress((void**)&WOl, g_WOl);
    cudaGetSymbolAddress((void**)&GWh, g_GWh); cudaGetSymbolAddress((void**)&GWl, g_GWl);
    cudaGetSymbolAddress((void**)&UWh, g_UWh); cudaGetSymbolAddress((void**)&UWl, g_UWl);
    cudaGetSymbolAddress((void**)&DWh, g_DWh); cudaGetSymbolAddress((void**)&DWl, g_DWl);
    cudaGetSymbolAddress((void**)&Hh,  g_Hh);  cudaGetSymbolAddress((void**)&Hl,  g_Hl);
    cudaGetSymbolAddress((void**)&ATh, g_ATh); cudaGetSymbolAddress((void**)&ATl, g_ATl);
    cudaGetSymbolAddress((void**)&Gh,  g_Gh);  cudaGetSymbolAddress((void**)&Gl,  g_Gl);

    cudaFuncSetAttribute(attn_k, cudaFuncAttributeMaxDynamicSharedMemorySize,
                         ATT_SMEM_BYTES);

    dim3 blk(256);
    // prep: PM = pm0+pm1; weights rotated (rope-folded) + split to bf16 hi/lo
    pmsum_k        <<<4096,  blk>>>(pm, PM);
    rotate_split_k <<<4096,  blk>>>(wq, WQh, WQl, D_DIM / 2);
    rotate_split_k <<<512,   blk>>>(wk, WKh, WKl, KV_DIM / 2);
    split_k        <<<512,   blk>>>(wv, WVh, WVl);
    split_k        <<<4096,  blk>>>(wo, WOh, WOl);
    split_k        <<<11264, blk>>>(gw, GWh, GWl);
    split_k        <<<11264, blk>>>(uw, UWh, UWl);
    split_k        <<<11264, blk>>>(dw, DWh, DWl);

    // attention sublayer
    rmsnorm_bf_k<<<BSL, blk>>>(x, wna, Hh, Hl);
    mma_gemm<1,0><<<dim3(D_DIM/TBN,  BSL/TBM), blk>>>(Hh, Hl, WQh, WQl, Qp, nullptr, nullptr, BSL, D_DIM,  D_DIM, PM);
    mma_gemm<1,0><<<dim3(KV_DIM/TBN, BSL/TBM), blk>>>(Hh, Hl, WKh, WKl, Kp, nullptr, nullptr, BSL, KV_DIM, D_DIM, PM);
    mma_gemm<0,0><<<dim3(KV_DIM/TBN, BSL/TBM), blk>>>(Hh, Hl, WVh, WVl, Vp, nullptr, nullptr, BSL, KV_DIM, D_DIM, nullptr);
    attn_k<<<dim3(S_LEN/64, 64), blk, ATT_SMEM_BYTES>>>(Qp, Kp, Vp, ATh, ATl);
    mma_gemm<2,0><<<dim3(D_DIM/TBN,  BSL/TBM), blk>>>(ATh, ATl, WOh, WOl, X2, nullptr, nullptr, BSL, D_DIM, D_DIM, x);

    // feedforward sublayer (SwiGLU)
    rmsnorm_bf_k<<<BSL, blk>>>(X2, wnf, Hh, Hl);
    mma_gemm<3,0><<<dim3(DFF_DIM/TBN, BSL/TBM), blk>>>(Hh, Hl, GWh, GWl, Gs, nullptr, nullptr, BSL, DFF_DIM, D_DIM, nullptr);
    mma_gemm<4,1><<<dim3(DFF_DIM/TBN, BSL/TBM), blk>>>(Hh, Hl, UWh, UWl, nullptr, Gh, Gl,      BSL, DFF_DIM, D_DIM, Gs);
    mma_gemm<2,0><<<dim3(D_DIM/TBN,   BSL/TBM), blk>>>(Gh, Gl, DWh, DWl, out, nullptr, nullptr, BSL, D_DIM, DFF_DIM, X2);
}

// round 13
// speedup vs baseline: 1.0007x; 1.0007x over previous
#include <cuda_runtime.h>
#include <cuda_bf16.h>
#include <math.h>

// ---------------- problem constants ----------------
#define S_LEN   2048
#define D_DIM   2048
#define KV_DIM  256
#define DFF_DIM 5632
#define BSL     4096          // B * S
#define EPSV    1e-6f

typedef __nv_bfloat16 bf16;

// ---------------- scratch (device globals; no allocation allowed) ----------
__device__ float g_PM [(size_t)S_LEN * D_DIM ];     // pm0 + pm1
// split (hi/lo) bf16 weights, rope folded into WQ/WK
__device__ bf16 g_WQh[(size_t)D_DIM  * D_DIM ], g_WQl[(size_t)D_DIM  * D_DIM ];
__device__ bf16 g_WKh[(size_t)KV_DIM * D_DIM ], g_WKl[(size_t)KV_DIM * D_DIM ];
__device__ bf16 g_WVh[(size_t)KV_DIM * D_DIM ], g_WVl[(size_t)KV_DIM * D_DIM ];
__device__ bf16 g_WOh[(size_t)D_DIM  * D_DIM ], g_WOl[(size_t)D_DIM  * D_DIM ];
__device__ bf16 g_GWh[(size_t)DFF_DIM* D_DIM ], g_GWl[(size_t)DFF_DIM* D_DIM ];
__device__ bf16 g_UWh[(size_t)DFF_DIM* D_DIM ], g_UWl[(size_t)DFF_DIM* D_DIM ];
__device__ bf16 g_DWh[(size_t)D_DIM  *DFF_DIM], g_DWl[(size_t)D_DIM  *DFF_DIM];
// split activations
__device__ bf16 g_Hh [(size_t)BSL * D_DIM ], g_Hl [(size_t)BSL * D_DIM ];
__device__ bf16 g_ATh[(size_t)BSL * D_DIM ], g_ATl[(size_t)BSL * D_DIM ];
__device__ bf16 g_Gh [(size_t)BSL * DFF_DIM], g_Gl[(size_t)BSL * DFF_DIM];
// fp32 intermediates
__device__ float g_Q  [(size_t)BSL * D_DIM ];
__device__ float g_K  [(size_t)BSL * KV_DIM];
__device__ float g_V  [(size_t)BSL * KV_DIM];
__device__ float g_X2 [(size_t)BSL * D_DIM ];
__device__ float g_Gs [(size_t)BSL * DFF_DIM];

// ---------------- helpers ----------------
__device__ __forceinline__ void split_f(float a, bf16 &h, bf16 &l) {
    h = __float2bfloat16(a);
    l = __float2bfloat16(a - __bfloat162float(h));
}

__device__ __forceinline__ void ldsm4(unsigned &r0, unsigned &r1,
                                      unsigned &r2, unsigned &r3, unsigned addr) {
    asm volatile("ldmatrix.sync.aligned.m8n8.x4.shared.b16 {%0,%1,%2,%3}, [%4];"
                 : "=r"(r0), "=r"(r1), "=r"(r2), "=r"(r3) : "r"(addr));
}
__device__ __forceinline__ void ldsm2(unsigned &r0, unsigned &r1, unsigned addr) {
    asm volatile("ldmatrix.sync.aligned.m8n8.x2.shared.b16 {%0,%1}, [%2];"
                 : "=r"(r0), "=r"(r1) : "r"(addr));
}
__device__ __forceinline__ void mma_bf16(float* c, const unsigned* a, const unsigned* b) {
    asm volatile("mma.sync.aligned.m16n8k16.row.col.f32.bf16.bf16.f32 "
                 "{%0,%1,%2,%3}, {%4,%5,%6,%7}, {%8,%9}, {%0,%1,%2,%3};"
                 : "+f"(c[0]), "+f"(c[1]), "+f"(c[2]), "+f"(c[3])
                 : "r"(a[0]), "r"(a[1]), "r"(a[2]), "r"(a[3]),
                   "r"(b[0]), "r"(b[1]));
}

// ---------------- prep kernels ----------------
__global__ void pmsum_k(const float* __restrict__ pm, float* __restrict__ out) {
    size_t i = ((size_t)blockIdx.x * 256 + threadIdx.x) * 4;
    float4 a = *(const float4*)&pm[i];
    float4 b = *(const float4*)&pm[(size_t)S_LEN * D_DIM + i];
    *(float4*)&out[i] = make_float4(a.x + b.x, a.y + b.y, a.z + b.z, a.w + b.w);
}

__device__ __forceinline__ void store_split4(bf16* oh, bf16* ol, size_t i, float4 v) {
    bf16 h0, l0, h1, l1, h2, l2, h3, l3;
    split_f(v.x, h0, l0); split_f(v.y, h1, l1);
    split_f(v.z, h2, l2); split_f(v.w, h3, l3);
    *(__nv_bfloat162*)&oh[i]     = __halves2bfloat162(h0, h1);
    *(__nv_bfloat162*)&oh[i + 2] = __halves2bfloat162(h2, h3);
    *(__nv_bfloat162*)&ol[i]     = __halves2bfloat162(l0, l1);
    *(__nv_bfloat162*)&ol[i + 2] = __halves2bfloat162(l2, l3);
}

__global__ void split_k(const float* __restrict__ w, bf16* __restrict__ oh,
                        bf16* __restrict__ ol) {
    size_t i = ((size_t)blockIdx.x * 256 + threadIdx.x) * 4;
    store_split4(oh, ol, i, *(const float4*)&w[i]);
}

// rope-rotate rows then split: out[c][k] = sgn * w[src][k]   (K dim = 2048)
__global__ void rotate_split_k(const float* __restrict__ w, bf16* __restrict__ oh,
                               bf16* __restrict__ ol, int half) {
    size_t i = ((size_t)blockIdx.x * 256 + threadIdx.x) * 4;
    int c = (int)(i >> 11);
    int k = (int)(i & 2047);
    int src = (c < half) ? (c + half) : (c - half);
    float sgn = (c < half) ? -1.f : 1.f;
    float4 v = *(const float4*)&w[(size_t)src * D_DIM + k];
    store_split4(oh, ol, i, make_float4(sgn*v.x, sgn*v.y, sgn*v.z, sgn*v.w));
}

// ---------------- rmsnorm -> split bf16 ----------------
__global__ __launch_bounds__(256) void rmsnorm_bf_k(const float* __restrict__ x,
                                                    const float* __restrict__ w,
                                                    bf16* __restrict__ oh,
                                                    bf16* __restrict__ ol) {
    int row = blockIdx.x;
    const float* xr = x + (size_t)row * D_DIM;
    size_t obase = (size_t)row * D_DIM;
    int t = threadIdx.x;
    float4 v0 = *(const float4*)&xr[t * 4];
    float4 v1 = *(const float4*)&xr[1024 + t * 4];
    float ss = v0.x*v0.x + v0.y*v0.y + v0.z*v0.z + v0.w*v0.w
             + v1.x*v1.x + v1.y*v1.y + v1.z*v1.z + v1.w*v1.w;
    #pragma unroll
    for (int off = 16; off; off >>= 1) ss += __shfl_xor_sync(0xffffffffu, ss, off);
    __shared__ float red[8];
    if ((t & 31) == 0) red[t >> 5] = ss;
    __syncthreads();
    float tot = red[0]+red[1]+red[2]+red[3]+red[4]+red[5]+red[6]+red[7];
    float sc = 1.f / (sqrtf(tot * (1.f / 2048.f) + EPSV) + EPSV);
    float4 w0 = *(const float4*)&w[t * 4];
    float4 w1 = *(const float4*)&w[1024 + t * 4];
    store_split4(oh, ol, obase + t * 4,
                 make_float4(v0.x*sc*w0.x, v0.y*sc*w0.y, v0.z*sc*w0.z, v0.w*sc*w0.w));
    store_split4(oh, ol, obase + 1024 + t * 4,
                 make_float4(v1.x*sc*w1.x, v1.y*sc*w1.y, v1.z*sc*w1.z, v1.w*sc*w1.w));
}

// ---------------- tensor-core GEMM (3xbf16 split, fp32 accuracy) ------------
//   C[M,N] = (Ah+Al)[M,K] @ (Bh+Bl)[N,K]^T   (Al*Bl term dropped)
// EPI: 0 plain | 1 *PM[(r&2047)*D+c] | 2 +aux[r*N+c] | 3 silu | 4 *aux[r*N+c]
// OUT: 0 fp32 C | 1 split bf16 (Ch, Cl)
#define TBM 128
#define TBN 128
#define TBK 32
#define SROW 40      // 32 + 8 pad -> 80B stride, conflict-free ldmatrix

template<int EPI>
__device__ __forceinline__ float epi_apply(float x, const float* __restrict__ aux,
                                           int r, int c, int N) {
    if (EPI == 1)      x *= aux[(size_t)(r & (S_LEN - 1)) * D_DIM + c];
    else if (EPI == 2) x += aux[(size_t)r * N + c];
    else if (EPI == 3) x  = x / (1.f + __expf(-x));
    else if (EPI == 4) x *= aux[(size_t)r * N + c];
    return x;
}

template<int EPI, int OUT>
__global__ __launch_bounds__(256) void mma_gemm(const bf16* __restrict__ Ah,
                                                const bf16* __restrict__ Al,
                                                const bf16* __restrict__ Bh,
                                                const bf16* __restrict__ Bl,
                                                float* __restrict__ C,
                                                bf16* __restrict__ Ch,
                                                bf16* __restrict__ Cl,
                                                int M, int N, int K,
                                                const float* __restrict__ aux) {
    __shared__ __align__(16) bf16 sAh[TBM * SROW];
    __shared__ __align__(16) bf16 sAl[TBM * SROW];
    __shared__ __align__(16) bf16 sBh[TBN * SROW];
    __shared__ __align__(16) bf16 sBl[TBN * SROW];

    int t = threadIdx.x;
    int lane = t & 31, wid = t >> 5;
    int wm = wid & 1, wn = wid >> 1;       // 2 x 4 warp grid, warp tile 64x32
    int m0 = blockIdx.y * TBM, n0 = blockIdx.x * TBN;

    // global loads: each thread loads a 16-elem row segment of each tile
    int lr = t >> 1;                // 0..127
    int lcb = (t & 1) * 16;         // 0 / 16
    const bf16* pAh = Ah + (size_t)(m0 + lr) * K + lcb;
    const bf16* pAl = Al + (size_t)(m0 + lr) * K + lcb;
    const bf16* pBh = Bh + (size_t)(n0 + lr) * K + lcb;
    const bf16* pBl = Bl + (size_t)(n0 + lr) * K + lcb;

    uint4 rah0 = *(const uint4*)(pAh),     rah1 = *(const uint4*)(pAh + 8);
    uint4 ral0 = *(const uint4*)(pAl),     ral1 = *(const uint4*)(pAl + 8);
    uint4 rbh0 = *(const uint4*)(pBh),     rbh1 = *(const uint4*)(pBh + 8);
    uint4 rbl0 = *(const uint4*)(pBl),     rbl1 = *(const uint4*)(pBl + 8);

    float acc[4][4][4];
    #pragma unroll
    for (int i = 0; i < 4; i++)
        #pragma unroll
        for (int j = 0; j < 4; j++)
            #pragma unroll
            for (int k = 0; k < 4; k++) acc[i][j][k] = 0.f;

    unsigned bAh = (unsigned)__cvta_generic_to_shared(sAh);
    unsigned bAl = (unsigned)__cvta_generic_to_shared(sAl);
    unsigned bBh = (unsigned)__cvta_generic_to_shared(sBh);
    unsigned bBl = (unsigned)__cvta_generic_to_shared(sBl);

    // ldmatrix lane offsets (bytes)
    unsigned aoff = ((unsigned)((wm * 64 + (lane & 15)) * SROW + ((lane & 16) >> 1))) * 2;
    unsigned boff = ((unsigned)((wn * 32 + (lane & 7)) * SROW + (lane & 8))) * 2;
    unsigned soff = (unsigned)(lr * SROW + lcb);   // element offset for stores

    for (int k0 = 0; k0 < K; k0 += TBK) {
        __syncthreads();
        *(uint4*)&sAh[soff] = rah0;  *(uint4*)&sAh[soff + 8] = rah1;
        *(uint4*)&sAl[soff] = ral0;  *(uint4*)&sAl[soff + 8] = ral1;
        *(uint4*)&sBh[soff] = rbh0;  *(uint4*)&sBh[soff + 8] = rbh1;
        *(uint4*)&sBl[soff] = rbl0;  *(uint4*)&sBl[soff + 8] = rbl1;
        __syncthreads();

        if (k0 + TBK < K) {
            int kn = k0 + TBK;
            rah0 = *(const uint4*)(pAh + kn);  rah1 = *(const uint4*)(pAh + kn + 8);
            ral0 = *(const uint4*)(pAl + kn);  ral1 = *(const uint4*)(pAl + kn + 8);
            rbh0 = *(const uint4*)(pBh + kn);  rbh1 = *(const uint4*)(pBh + kn + 8);
            rbl0 = *(const uint4*)(pBl + kn);  rbl1 = *(const uint4*)(pBl + kn + 8);
        }

        #pragma unroll
        for (int ks = 0; ks < 2; ks++) {
            unsigned fah[4][4], fal[4][4], fbh[4][2], fbl[4][2];
            #pragma unroll
            for (int mi = 0; mi < 4; mi++) {
                unsigned od = aoff + (unsigned)(mi * 16 * SROW * 2) + (unsigned)(ks * 32);
                ldsm4(fah[mi][0], fah[mi][1], fah[mi][2], fah[mi][3], bAh + od);
                ldsm4(fal[mi][0], fal[mi][1], fal[mi][2], fal[mi][3], bAl + od);
            }
            #pragma unroll
            for (int ni = 0; ni < 4; ni++) {
                unsigned od = boff + (unsigned)(ni * 8 * SROW * 2) + (unsigned)(ks * 32);
                ldsm2(fbh[ni][0], fbh[ni][1], bBh + od);
                ldsm2(fbl[ni][0], fbl[ni][1], bBl + od);
            }
            #pragma unroll
            for (int mi = 0; mi < 4; mi++)
                #pragma unroll
                for (int ni = 0; ni < 4; ni++) {
                    mma_bf16(acc[mi][ni], fah[mi], fbh[ni]);
                    mma_bf16(acc[mi][ni], fah[mi], fbl[ni]);
                    mma_bf16(acc[mi][ni], fal[mi], fbh[ni]);
                }
        }
    }

    // ------------- epilogue -------------
    int gid = lane >> 2;
    int c2  = (lane & 3) * 2;
    #pragma unroll
    for (int mi = 0; mi < 4; mi++) {
        #pragma unroll
        for (int ni = 0; ni < 4; ni++) {
            int r = m0 + wm * 64 + mi * 16 + gid;
            int c = n0 + wn * 32 + ni * 8 + c2;
            #pragma unroll
            for (int half = 0; half < 2; half++) {
                int rr = r + half * 8;
                float v0 = epi_apply<EPI>(acc[mi][ni][half*2 + 0], aux, rr, c,   N);
                float v1 = epi_apply<EPI>(acc[mi][ni][half*2 + 1], aux, rr, c+1, N);
                if (OUT == 0) {
                    *(float2*)&C[(size_t)rr * N + c] = make_float2(v0, v1);
                } else {
                    bf16 h0, l0, h1, l1;
                    split_f(v0, h0, l0);  split_f(v1, h1, l1);
                    *(__nv_bfloat162*)&Ch[(size_t)rr * N + c] = __halves2bfloat162(h0, h1);
                    *(__nv_bfloat162*)&Cl[(size_t)rr * N + c] = __halves2bfloat162(l0, l1);
                }
            }
        }
    }
}

// ---------------- attention: flash-style 64x64 streaming tile ----------------
// attn = exp(Q K^T * scale) ; out = (attn @ V) / (rowsum + 1)  -> split bf16
#define ATT_SMEM_BYTES ((4096 + 4160 + 4096) * 4)   // Qs[64*64] KP[64*65] Vs[64*64]

__global__ __launch_bounds__(256) void attn_k(const float* __restrict__ Qg,
                                              const float* __restrict__ Kg,
                                              const float* __restrict__ Vg,
                                              bf16* __restrict__ Oh,
                                              bf16* __restrict__ Ol) {
    extern __shared__ __align__(16) float sm[];
    float* Qs = sm;
    float* KP = sm + 4096;        // K tile, then reused for P = exp(scores)
    float* Vs = sm + 4096 + 4160;
    const float scale = 1.0f / (16.0f + 1e-6f);   // 1/(sqrt(256)+eps)

    int t  = threadIdx.x;
    int tx = t & 15, ty = t >> 4;
    int q0 = blockIdx.x << 6;
    int bh = blockIdx.y;
    int b = bh >> 5, hd = bh & 31;
    const float* Qb = Qg + ((size_t)(b * S_LEN + q0)) * D_DIM + hd * 64;
    const float* Kb = Kg + (size_t)b * S_LEN * KV_DIM + (hd & 3) * 64;
    const float* Vb = Vg + (size_t)b * S_LEN * KV_DIM + (hd & 3) * 64;

    int lr = t >> 2;
    int lc = (t & 3) << 4;
    {   // load + pre-scale Q tile
        const float* src = Qb + (size_t)lr * D_DIM + lc;
        float* dst = Qs + lr * 64 + lc;
        #pragma unroll
        for (int i = 0; i < 16; i += 4) {
            float4 v = *(const float4*)(src + i);
            *(float4*)(dst + i) = make_float4(v.x*scale, v.y*scale, v.z*scale, v.w*scale);
        }
    }

    float accO[4][4];
    float den[4];
    #pragma unroll
    for (int i = 0; i < 4; i++) {
        den[i] = 0.f;
        #pragma unroll
        for (int j = 0; j < 4; j++) accO[i][j] = 0.f;
    }

    for (int kt = 0; kt < 32; kt++) {
        __syncthreads();
        {   // load K (stride-65 rows) and V tiles
            const float* ks = Kb + (size_t)(kt * 64 + lr) * KV_DIM + lc;
            const float* vs = Vb + (size_t)(kt * 64 + lr) * KV_DIM + lc;
            #pragma unroll
            for (int i = 0; i < 16; i += 4) {
                float4 kv = *(const float4*)(ks + i);
                KP[lr*65 + lc + i + 0] = kv.x;
                KP[lr*65 + lc + i + 1] = kv.y;
                KP[lr*65 + lc + i + 2] = kv.z;
                KP[lr*65 + lc + i + 3] = kv.w;
                *(float4*)(Vs + lr*64 + lc + i) = *(const float4*)(vs + i);
            }
        }
        __syncthreads();
        float sc[4][4] = {};
        #pragma unroll 8
        for (int k = 0; k < 64; k++) {
            float q[4], kk[4];
            #pragma unroll
            for (int i = 0; i < 4; i++) q[i]  = Qs[(4*ty + i) * 64 + k];
            #pragma unroll
            for (int j = 0; j < 4; j++) kk[j] = KP[(4*tx + j) * 65 + k];
            #pragma unroll
            for (int i = 0; i < 4; i++)
                #pragma unroll
                for (int j = 0; j < 4; j++) sc[i][j] += q[i] * kk[j];
        }
        __syncthreads();
        #pragma unroll
        for (int i = 0; i < 4; i++)
            #pragma unroll
            for (int j = 0; j < 4; j++)
                KP[(4*ty + i) * 65 + 4*tx + j] = __expf(sc[i][j]);
        __syncthreads();
        #pragma unroll 8
        for (int k = 0; k < 64; k++) {
            float p[4];
            #pragma unroll
            for (int i = 0; i < 4; i++) p[i] = KP[(4*ty + i) * 65 + k];
            float4 vv = *(const float4*)&Vs[k * 64 + 4*tx];
            #pragma unroll
            for (int i = 0; i < 4; i++) {
                accO[i][0] += p[i] * vv.x;
                accO[i][1] += p[i] * vv.y;
                accO[i][2] += p[i] * vv.z;
                accO[i][3] += p[i] * vv.w;
                den[i]     += p[i];
            }
        }
    }

    size_t obase = ((size_t)(b * S_LEN + q0)) * D_DIM + hd * 64;
    #pragma unroll
    for (int i = 0; i < 4; i++) {
        float inv = 1.f / (den[i] + 1.f);
        float v0 = accO[i][0]*inv, v1 = accO[i][1]*inv;
        float v2 = accO[i][2]*inv, v3 = accO[i][3]*inv;
        bf16 h0,l0,h1,l1,h2,l2,h3,l3;
        split_f(v0,h0,l0); split_f(v1,h1,l1); split_f(v2,h2,l2); split_f(v3,h3,l3);
        size_t off = obase + (size_t)(4*ty + i) * D_DIM + 4*tx;
        *(__nv_bfloat162*)&Oh[off]     = __halves2bfloat162(h0, h1);
        *(__nv_bfloat162*)&Oh[off + 2] = __halves2bfloat162(h2, h3);
        *(__nv_bfloat162*)&Ol[off]     = __halves2bfloat162(l0, l1);
        *(__nv_bfloat162*)&Ol[off + 2] = __halves2bfloat162(l2, l3);
    }
}

// ---------------- launcher ----------------
extern "C" void kernel_launch(void* const* d_in, const int* in_sizes, int n_in,
                              void* d_out, int out_size) {
    (void)in_sizes; (void)n_in; (void)out_size;
    const float* x   = (const float*)d_in[0];
    const float* pm  = (const float*)d_in[1];
    const float* wna = (const float*)d_in[2];
    const float* wnf = (const float*)d_in[3];
    const float* wq  = (const float*)d_in[4];
    const float* wk  = (const float*)d_in[5];
    const float* wv  = (const float*)d_in[6];
    const float* wo  = (const float*)d_in[7];
    const float* gw  = (const float*)d_in[8];
    const float* uw  = (const float*)d_in[9];
    const float* dw  = (const float*)d_in[10];
    float* out = (float*)d_out;

    float *PM, *Qp, *Kp, *Vp, *X2, *Gs;
    bf16 *WQh,*WQl,*WKh,*WKl,*WVh,*WVl,*WOh,*WOl,*GWh,*GWl,*UWh,*UWl,*DWh,*DWl;
    bf16 *Hh,*Hl,*ATh,*ATl,*Gh,*Gl;
    cudaGetSymbolAddress((void**)&PM,  g_PM);
    cudaGetSymbolAddress((void**)&Qp,  g_Q);
    cudaGetSymbolAddress((void**)&Kp,  g_K);
    cudaGetSymbolAddress((void**)&Vp,  g_V);
    cudaGetSymbolAddress((void**)&X2,  g_X2);
    cudaGetSymbolAddress((void**)&Gs,  g_Gs);
    cudaGetSymbolAddress((void**)&WQh, g_WQh); cudaGetSymbolAddress((void**)&WQl, g_WQl);
    cudaGetSymbolAddress((void**)&WKh, g_WKh); cudaGetSymbolAddress((void**)&WKl, g_WKl);
    cudaGetSymbolAddress((void**)&WVh, g_WVh); cudaGetSymbolAddress((void**)&WVl, g_WVl);
    cudaGetSymbolAddress((void**)&WOh, g_WOh); cudaGetSymbolAddress((void**)&WOl, g_WOl);
    cudaGetSymbolAddress((void**)&GWh, g_GWh); cudaGetSymbolAddress((void**)&GWl, g_GWl);
    cudaGetSymbolAddress((void**)&UWh, g_UWh); cudaGetSymbolAddress((void**)&UWl, g_UWl);
    cudaGetSymbolAddress((void**)&DWh, g_DWh); cudaGetSymbolAddress((void**)&DWl, g_DWl);
    cudaGetSymbolAddress((void**)&Hh,  g_Hh);  cudaGetSymbolAddress((void**)&Hl,  g_Hl);
    cudaGetSymbolAddress((void**)&ATh, g_ATh); cudaGetSymbolAddress((void**)&ATl, g_ATl);
    cudaGetSymbolAddress((void**)&Gh,  g_Gh);  cudaGetSymbolAddress((void**)&Gl,  g_Gl);

    cudaFuncSetAttribute(attn_k, cudaFuncAttributeMaxDynamicSharedMemorySize,
                         ATT_SMEM_BYTES);

    dim3 blk(256);
    // prep: PM = pm0+pm1; weights rotated (rope-folded) + split to bf16 hi/lo
    pmsum_k        <<<4096,  blk>>>(pm, PM);
    rotate_split_k <<<4096,  blk>>>(wq, WQh, WQl, D_DIM / 2);
    rotate_split_k <<<512,   blk>>>(wk, WKh, WKl, KV_DIM / 2);
    split_k        <<<512,   blk>>>(wv, WVh, WVl);
    split_k        <<<4096,  blk>>>(wo, WOh, WOl);
    split_k        <<<11264, blk>>>(gw, GWh, GWl);
    split_k        <<<11264, blk>>>(uw, UWh, UWl);
    split_k        <<<11264, blk>>>(dw, DWh, DWl);

    // attention sublayer
    rmsnorm_bf_k<<<BSL, blk>>>(x, wna, Hh, Hl);
    mma_gemm<1,0><<<dim3(D_DIM/TBN,  BSL/TBM), blk>>>(Hh, Hl, WQh, WQl, Qp, nullptr, nullptr, BSL, D_DIM,  D_DIM, PM);
    mma_gemm<1,0><<<dim3(KV_DIM/TBN, BSL/TBM), blk>>>(Hh, Hl, WKh, WKl, Kp, nullptr, nullptr, BSL, KV_DIM, D_DIM, PM);
    mma_gemm<0,0><<<dim3(KV_DIM/TBN, BSL/TBM), blk>>>(Hh, Hl, WVh, WVl, Vp, nullptr, nullptr, BSL, KV_DIM, D_DIM, nullptr);
    attn_k<<<dim3(S_LEN/64, 64), blk, ATT_SMEM_BYTES>>>(Qp, Kp, Vp, ATh, ATl);
    mma_gemm<2,0><<<dim3(D_DIM/TBN,  BSL/TBM), blk>>>(ATh, ATl, WOh, WOl, X2, nullptr, nullptr, BSL, D_DIM, D_DIM, x);

    // feedforward sublayer (SwiGLU)
    rmsnorm_bf_k<<<BSL, blk>>>(X2, wnf, Hh, Hl);
    mma_gemm<3,0><<<dim3(DFF_DIM/TBN, BSL/TBM), blk>>>(Hh, Hl, GWh, GWl, Gs, nullptr, nullptr, BSL, DFF_DIM, D_DIM, nullptr);
    mma_gemm<4,1><<<dim3(DFF_DIM/TBN, BSL/TBM), blk>>>(Hh, Hl, UWh, UWl, nullptr, Gh, Gl,      BSL, DFF_DIM, D_DIM, Gs);
    mma_gemm<2,0><<<dim3(D_DIM/TBN,   BSL/TBM), blk>>>(Gh, Gl, DWh, DWl, out, nullptr, nullptr, BSL, D_DIM, DFF_DIM, X2);
}